// round 6
// baseline (speedup 1.0000x reference)
#include <cuda_runtime.h>

typedef unsigned long long ull;

#define HH 192
#define BB 16
#define NPIX (BB*2*HH*HH)

// ---------- packed f32x2 helpers (sm_103a) ----------
__device__ __forceinline__ ull pk2(float x, float y){ ull r; asm("mov.b64 %0,{%1,%2};":"=l"(r):"f"(x),"f"(y)); return r; }
__device__ __forceinline__ ull dup2(float x){ return pk2(x,x); }
__device__ __forceinline__ void unpk2(ull v, float&x, float&y){ asm("mov.b64 {%0,%1},%2;":"=f"(x),"=f"(y):"l"(v)); }
__device__ __forceinline__ ull ffma2(ull a, ull b, ull c){ ull d; asm("fma.rn.f32x2 %0,%1,%2,%3;":"=l"(d):"l"(a),"l"(b),"l"(c)); return d; }
__device__ __forceinline__ ull fmul2(ull a, ull b){ ull d; asm("mul.rn.f32x2 %0,%1,%2;":"=l"(d):"l"(a),"l"(b)); return d; }
__device__ __forceinline__ ull fadd2(ull a, ull b){ ull d; asm("add.rn.f32x2 %0,%1,%2;":"=l"(d):"l"(a),"l"(b)); return d; }

// ---------- packed constants, 16B-vectorized ----------
struct ConstBlob {
  ulonglong2 kp[3][25];  // kp[p][i*5+j] = (stencil 2p, stencil 2p+1) tap, lanes dup
  ulonglong2 w0p[12];    // .x = p weight(i), .y = q weight(i); lanes = poly k0,k1
  ulonglong2 w1p[13];    // .x = r, .y = s
  ulonglong2 b01;        // .x = b0(p), .y = b0(q)
  ulonglong2 b11;        // .x = b1(r), .y = b1(s)
  ulonglong2 gw0p[2];    // [off-1]; .x = u=0 pack, .y = u=1 pack
  ulonglong2 gw1p[2];
  ull wf[14];
  ull bf;
  ull gwf[2];
};

__constant__ ConstBlob cb;
__device__ ConstBlob g_stage;
__device__ float g_uh[NPIX];
__device__ float g_ua[NPIX];
__device__ float g_ub[NPIX];

__global__ void prep_kernel(const float* __restrict__ kern,
                            const float* __restrict__ w0, const float* __restrict__ b0,
                            const float* __restrict__ w1, const float* __restrict__ b1,
                            const float* __restrict__ wf, const float* __restrict__ bf)
{
  int t = threadIdx.x;
  const double dDX = 0.0327249;
  const float s1 = (float)(1.0/dDX);
  const float s2 = (float)(1.0/(dDX*dDX));
  const float sc[6] = {1.f, s1, s1, s2, s2, s2};
  if (t < 75) {
    int p = t/25, e = t%25;
    int d0 = 2*p, d1 = 2*p+1;
    ulonglong2 v;
    v.x = dup2(kern[d0*25 + e] * sc[d0]);
    v.y = dup2(kern[d1*25 + e] * sc[d1]);
    g_stage.kp[p][e] = v;
  }
  if (t == 0) {
    for (int i = 0; i < 12; i++) {
      ulonglong2 a;
      a.x = pk2(w0[i],    w0[24+i]);
      a.y = pk2(w0[12+i], w0[24+12+i]);
      g_stage.w0p[i] = a;
    }
    for (int i = 0; i < 13; i++) {
      ulonglong2 a;
      a.x = pk2(w1[i],    w1[26+i]);
      a.y = pk2(w1[13+i], w1[26+13+i]);
      g_stage.w1p[i] = a;
    }
    { ulonglong2 a; a.x = pk2(b0[0], b0[2]); a.y = pk2(b0[1], b0[3]); g_stage.b01 = a; }
    { ulonglong2 a; a.x = pk2(b1[0], b1[2]); a.y = pk2(b1[1], b1[3]); g_stage.b11 = a; }
    for (int i = 0; i < 14; i++) g_stage.wf[i] = pk2(wf[i], wf[14+i]);
    g_stage.bf = pk2(bf[0], bf[1]);
    for (int o = 0; o < 2; o++) {
      ulonglong2 a, c;
      a.x = pk2(w0[1+o],      w0[24 + 7+o]);
      a.y = pk2(w0[12 + 1+o], w0[24 + 12 + 7+o]);
      g_stage.gw0p[o] = a;
      c.x = pk2(w1[1+o],      w1[26 + 7+o]);
      c.y = pk2(w1[13 + 1+o], w1[26 + 13 + 7+o]);
      g_stage.gw1p[o] = c;
      g_stage.gwf[o] = pk2(wf[1+o], wf[14 + 7+o]);
    }
  }
}

// SymNet + gradient + upwind + final poly for one pixel.
// acc[0..5]=base feats (a0..a5), acc[6]=t6 (=-f01), acc[7]=t7 (=-f10).
__device__ __forceinline__ void poly_pixel(const ull* __restrict__ acc, float& ua0, float& ua1)
{
  float X[12];
  unpk2(acc[0], X[0], X[6]); unpk2(acc[1], X[1], X[7]); unpk2(acc[2], X[2], X[8]);
  unpk2(acc[3], X[3], X[9]); unpk2(acc[4], X[4], X[10]); unpk2(acc[5], X[5], X[11]);
  float n6x, n6y, n7x, n7y;
  unpk2(acc[6], n6x, n6y);
  unpk2(acc[7], n7x, n7y);

  ull p2 = cb.b01.x, q2 = cb.b01.y, rl = cb.b11.x, sl = cb.b11.y, ol = cb.bf;
  #pragma unroll
  for (int i = 0; i < 12; i++) {
    ull xd = dup2(X[i]);
    const ulonglong2 wa = cb.w0p[i];
    const ulonglong2 wb = cb.w1p[i];
    p2 = ffma2(wa.x, xd, p2);
    q2 = ffma2(wa.y, xd, q2);
    rl = ffma2(wb.x, xd, rl);
    sl = ffma2(wb.y, xd, sl);
    ol = ffma2(cb.wf[i], xd, ol);
  }
  const ulonglong2 wm = cb.w1p[12];
  ull m1 = fmul2(p2, q2);
  ull r2 = ffma2(wm.x, m1, rl);
  ull s2 = ffma2(wm.y, m1, sl);

  ull g2[2];
  #pragma unroll
  for (int o = 0; o < 2; o++) {
    const ulonglong2 ga = cb.gw0p[o];
    const ulonglong2 gc = cb.gw1p[o];
    ull dm1 = fadd2(fmul2(q2, ga.x), fmul2(p2, ga.y));
    ull dr  = ffma2(wm.x, dm1, gc.x);
    ull ds  = ffma2(wm.y, dm1, gc.y);
    ull dm2 = fadd2(fmul2(s2, dr), fmul2(r2, ds));
    ull g   = ffma2(cb.wf[12], dm1, cb.gwf[o]);
    g2[o]   = ffma2(cb.wf[13], dm2, g);
  }
  float g01a, g01b, g10a, g10b;
  unpk2(g2[0], g01a, g01b);
  unpk2(g2[1], g10a, g10b);

  float d1 = (g01a > 0.f) ? 0.f : (-n6x - X[1]);
  float d7 = (g01b > 0.f) ? 0.f : (-n6y - X[7]);
  float d2 = (g10a > 0.f) ? 0.f : (-n7x - X[2]);
  float d8 = (g10b > 0.f) ? 0.f : (-n7y - X[8]);
  ull D1 = dup2(d1), D2 = dup2(d2), D7 = dup2(d7), D8 = dup2(d8);

  {
    const ulonglong2 c1 = cb.w0p[1], c2 = cb.w0p[2], c7 = cb.w0p[7], c8 = cb.w0p[8];
    p2 = ffma2(c1.x, D1, ffma2(c2.x, D2, ffma2(c7.x, D7, ffma2(c8.x, D8, p2))));
    q2 = ffma2(c1.y, D1, ffma2(c2.y, D2, ffma2(c7.y, D7, ffma2(c8.y, D8, q2))));
  }
  {
    const ulonglong2 c1 = cb.w1p[1], c2 = cb.w1p[2], c7 = cb.w1p[7], c8 = cb.w1p[8];
    rl = ffma2(c1.x, D1, ffma2(c2.x, D2, ffma2(c7.x, D7, ffma2(c8.x, D8, rl))));
    sl = ffma2(c1.y, D1, ffma2(c2.y, D2, ffma2(c7.y, D7, ffma2(c8.y, D8, sl))));
  }
  ol = ffma2(cb.wf[1], D1, ffma2(cb.wf[2], D2, ffma2(cb.wf[7], D7, ffma2(cb.wf[8], D8, ol))));

  m1 = fmul2(p2, q2);
  r2 = ffma2(wm.x, m1, rl);
  s2 = ffma2(wm.y, m1, sl);
  ull m2 = fmul2(r2, s2);
  ull o2 = ffma2(cb.wf[12], m1, ol);
  o2 = ffma2(cb.wf[13], m2, o2);
  unpk2(o2, ua0, ua1);
}

// out = ubase + coef*rhs(ueval); 2 vertically-adjacent pixels per thread,
// rolling-window conv so every constant load serves both pixels.
__global__ __launch_bounds__(256, 4)
void rhs_step(const float* __restrict__ ue, const float* __restrict__ ub,
              float coef, float* __restrict__ out)
{
  __shared__ ull tile[20][36];   // rows h0-2 .. h0+17

  const int tx = threadIdx.x, ty = threadIdx.y;   // 32 x 8
  const int tid = ty*32 + tx;
  const int w0_ = blockIdx.x*32, h0 = blockIdx.y*16, b = blockIdx.z;

  const float* u0 = ue + (size_t)b*2*HH*HH;
  const float* u1 = u0 + HH*HH;

  #pragma unroll
  for (int e = tid; e < 20*36; e += 256) {
    int r = e/36, c = e%36;
    int h = h0 + r - 2; if (h < 0) h += HH; if (h >= HH) h -= HH;
    int w = w0_ + c - 2; if (w < 0) w += HH; if (w >= HH) w -= HH;
    tile[r][c] = pk2(u0[h*HH+w], u1[h*HH+w]);
  }
  __syncthreads();

  const int ry = 2*ty;   // pixel0 row = h0+ry, pixel1 row = h0+ry+1

  ull acc0[8], acc1[8];
  #pragma unroll
  for (int d = 0; d < 8; d++) { acc0[d] = 0ull; acc1[d] = 0ull; }

  ull wA[5], wB[5];
  #pragma unroll
  for (int j = 0; j < 5; j++) wA[j] = tile[ry][tx+j];

  // Loop over kernel rows r: pixel0's window row r = tile[ry+r] (wA),
  // pixel1's = tile[ry+r+1] (wB). Constants of row r serve both pixels.
  #pragma unroll
  for (int r = 0; r < 5; r++) {
    #pragma unroll
    for (int j = 0; j < 5; j++) wB[j] = tile[ry+r+1][tx+j];
    #pragma unroll
    for (int j = 0; j < 5; j++) {
      const ulonglong2 k01 = cb.kp[0][r*5+j];
      const ulonglong2 k23 = cb.kp[1][r*5+j];
      const ulonglong2 k45 = cb.kp[2][r*5+j];
      const ull km = cb.kp[1][(4-r)*5+j].x;   // k10 tap from mirrored row -> t7
      acc0[0] = ffma2(k01.x, wA[j], acc0[0]);
      acc0[1] = ffma2(k01.y, wA[j], acc0[1]);
      acc0[2] = ffma2(k23.x, wA[j], acc0[2]);
      acc0[3] = ffma2(k23.y, wA[j], acc0[3]);
      acc0[4] = ffma2(k45.x, wA[j], acc0[4]);
      acc0[5] = ffma2(k45.y, wA[j], acc0[5]);
      acc0[6] = ffma2(k01.y, wA[4-j], acc0[6]);   // t6: width mirror
      acc0[7] = ffma2(km,    wA[j],   acc0[7]);   // t7: height mirror
      acc1[0] = ffma2(k01.x, wB[j], acc1[0]);
      acc1[1] = ffma2(k01.y, wB[j], acc1[1]);
      acc1[2] = ffma2(k23.x, wB[j], acc1[2]);
      acc1[3] = ffma2(k23.y, wB[j], acc1[3]);
      acc1[4] = ffma2(k45.x, wB[j], acc1[4]);
      acc1[5] = ffma2(k45.y, wB[j], acc1[5]);
      acc1[6] = ffma2(k01.y, wB[4-j], acc1[6]);
      acc1[7] = ffma2(km,    wB[j],   acc1[7]);
    }
    #pragma unroll
    for (int j = 0; j < 5; j++) wA[j] = wB[j];
  }

  const int h = h0 + ry, w = w0_ + tx;
  const size_t i0 = ((size_t)(b*2))*HH*HH + (size_t)h*HH + w;

  float a0, a1;
  poly_pixel(acc0, a0, a1);
  out[i0]         = ub[i0]         + coef*a0;
  out[i0 + HH*HH] = ub[i0 + HH*HH] + coef*a1;

  float c0, c1;
  poly_pixel(acc1, c0, c1);
  out[i0 + HH]         = ub[i0 + HH]         + coef*c0;
  out[i0 + HH + HH*HH] = ub[i0 + HH + HH*HH] + coef*c1;
}

extern "C" void kernel_launch(void* const* d_in, const int* in_sizes, int n_in,
                              void* d_out, int out_size)
{
  (void)in_sizes; (void)n_in; (void)out_size;
  const float* init = (const float*)d_in[0];
  const float* kern = (const float*)d_in[1];
  const float* w0   = (const float*)d_in[2];
  const float* b0   = (const float*)d_in[3];
  const float* w1   = (const float*)d_in[4];
  const float* b1   = (const float*)d_in[5];
  const float* wf   = (const float*)d_in[6];
  const float* bf   = (const float*)d_in[7];
  float* out = (float*)d_out;

  void *puh, *pua, *pub, *pstage;
  cudaGetSymbolAddress(&puh, g_uh);
  cudaGetSymbolAddress(&pua, g_ua);
  cudaGetSymbolAddress(&pub, g_ub);
  cudaGetSymbolAddress(&pstage, g_stage);

  prep_kernel<<<1, 128>>>(kern, w0, b0, w1, b1, wf, bf);
  cudaMemcpyToSymbolAsync(cb, pstage, sizeof(ConstBlob), 0, cudaMemcpyDeviceToDevice, 0);

  dim3 grid(HH/32, HH/16, BB);
  dim3 block(32, 8);

  const float DT = 0.2f;
  const float* ucur = init;
  for (int s = 0; s < 5; s++) {
    float* un = (s == 4) ? out : ((s & 1) ? (float*)pub : (float*)pua);
    rhs_step<<<grid, block>>>(ucur, ucur, DT*0.5f, (float*)puh);
    rhs_step<<<grid, block>>>((float*)puh, ucur, DT, un);
    ucur = un;
  }
}

// round 7
// speedup vs baseline: 1.3442x; 1.3442x over previous
#include <cuda_runtime.h>

typedef unsigned long long ull;

#define HH 192
#define BB 16
#define NPIX (BB*2*HH*HH)

// ---------- packed f32x2 helpers (sm_103a) ----------
__device__ __forceinline__ ull pk2(float x, float y){ ull r; asm("mov.b64 %0,{%1,%2};":"=l"(r):"f"(x),"f"(y)); return r; }
__device__ __forceinline__ ull dup2(float x){ return pk2(x,x); }
__device__ __forceinline__ void unpk2(ull v, float&x, float&y){ asm("mov.b64 {%0,%1},%2;":"=f"(x),"=f"(y):"l"(v)); }
__device__ __forceinline__ ull ffma2(ull a, ull b, ull c){ ull d; asm("fma.rn.f32x2 %0,%1,%2,%3;":"=l"(d):"l"(a),"l"(b),"l"(c)); return d; }
__device__ __forceinline__ ull fmul2(ull a, ull b){ ull d; asm("mul.rn.f32x2 %0,%1,%2;":"=l"(d):"l"(a),"l"(b)); return d; }
__device__ __forceinline__ ull fadd2(ull a, ull b){ ull d; asm("add.rn.f32x2 %0,%1,%2;":"=l"(d):"l"(a),"l"(b)); return d; }

// ---------- packed constants, 16B-vectorized ----------
struct ConstBlob {
  ulonglong2 kp[3][25];  // kp[p][i*5+j] = (stencil 2p, stencil 2p+1) tap, lanes dup
  ulonglong2 w0p[12];    // .x = p weight(i), .y = q weight(i); lanes = poly k0,k1
  ulonglong2 w1p[13];    // .x = r, .y = s
  ulonglong2 b01;        // .x = b0(p), .y = b0(q)
  ulonglong2 b11;        // .x = b1(r), .y = b1(s)
  ulonglong2 gw0p[2];    // [off-1]; .x = u=0 pack, .y = u=1 pack
  ulonglong2 gw1p[2];
  ull wf[14];
  ull bf;
  ull gwf[2];
};

__constant__ ConstBlob cb;
__device__ ConstBlob g_stage;
__device__ float g_uh[NPIX];
__device__ float g_ua[NPIX];
__device__ float g_ub[NPIX];

__global__ void prep_kernel(const float* __restrict__ kern,
                            const float* __restrict__ w0, const float* __restrict__ b0,
                            const float* __restrict__ w1, const float* __restrict__ b1,
                            const float* __restrict__ wf, const float* __restrict__ bf)
{
  int t = threadIdx.x;
  const double dDX = 0.0327249;
  const float s1 = (float)(1.0/dDX);
  const float s2 = (float)(1.0/(dDX*dDX));
  const float sc[6] = {1.f, s1, s1, s2, s2, s2};
  if (t < 75) {
    int p = t/25, e = t%25;
    int d0 = 2*p, d1 = 2*p+1;
    ulonglong2 v;
    v.x = dup2(kern[d0*25 + e] * sc[d0]);
    v.y = dup2(kern[d1*25 + e] * sc[d1]);
    g_stage.kp[p][e] = v;
  }
  if (t == 0) {
    for (int i = 0; i < 12; i++) {
      ulonglong2 a;
      a.x = pk2(w0[i],    w0[24+i]);
      a.y = pk2(w0[12+i], w0[24+12+i]);
      g_stage.w0p[i] = a;
    }
    for (int i = 0; i < 13; i++) {
      ulonglong2 a;
      a.x = pk2(w1[i],    w1[26+i]);
      a.y = pk2(w1[13+i], w1[26+13+i]);
      g_stage.w1p[i] = a;
    }
    { ulonglong2 a; a.x = pk2(b0[0], b0[2]); a.y = pk2(b0[1], b0[3]); g_stage.b01 = a; }
    { ulonglong2 a; a.x = pk2(b1[0], b1[2]); a.y = pk2(b1[1], b1[3]); g_stage.b11 = a; }
    for (int i = 0; i < 14; i++) g_stage.wf[i] = pk2(wf[i], wf[14+i]);
    g_stage.bf = pk2(bf[0], bf[1]);
    for (int o = 0; o < 2; o++) {
      ulonglong2 a, c;
      a.x = pk2(w0[1+o],      w0[24 + 7+o]);
      a.y = pk2(w0[12 + 1+o], w0[24 + 12 + 7+o]);
      g_stage.gw0p[o] = a;
      c.x = pk2(w1[1+o],      w1[26 + 7+o]);
      c.y = pk2(w1[13 + 1+o], w1[26 + 13 + 7+o]);
      g_stage.gw1p[o] = c;
      g_stage.gwf[o] = pk2(wf[1+o], wf[14 + 7+o]);
    }
  }
}

// SymNet + gradient + upwind + final poly for one pixel.
// acc[0..5]=base feats, acc[6]=t6 (=-f01), acc[7]=t7 (=-f10).
__device__ __forceinline__ void poly_pixel(const ull* __restrict__ acc, float& ua0, float& ua1)
{
  float X[12];
  unpk2(acc[0], X[0], X[6]); unpk2(acc[1], X[1], X[7]); unpk2(acc[2], X[2], X[8]);
  unpk2(acc[3], X[3], X[9]); unpk2(acc[4], X[4], X[10]); unpk2(acc[5], X[5], X[11]);
  float n6x, n6y, n7x, n7y;
  unpk2(acc[6], n6x, n6y);
  unpk2(acc[7], n7x, n7y);

  ull p2 = cb.b01.x, q2 = cb.b01.y, rl = cb.b11.x, sl = cb.b11.y, ol = cb.bf;
  #pragma unroll
  for (int i = 0; i < 12; i++) {
    ull xd = dup2(X[i]);
    const ulonglong2 wa = cb.w0p[i];
    const ulonglong2 wb = cb.w1p[i];
    p2 = ffma2(wa.x, xd, p2);
    q2 = ffma2(wa.y, xd, q2);
    rl = ffma2(wb.x, xd, rl);
    sl = ffma2(wb.y, xd, sl);
    ol = ffma2(cb.wf[i], xd, ol);
  }
  const ulonglong2 wm = cb.w1p[12];
  ull m1 = fmul2(p2, q2);
  ull r2 = ffma2(wm.x, m1, rl);
  ull s2 = ffma2(wm.y, m1, sl);

  ull g2[2];
  #pragma unroll
  for (int o = 0; o < 2; o++) {
    const ulonglong2 ga = cb.gw0p[o];
    const ulonglong2 gc = cb.gw1p[o];
    ull dm1 = fadd2(fmul2(q2, ga.x), fmul2(p2, ga.y));
    ull dr  = ffma2(wm.x, dm1, gc.x);
    ull ds  = ffma2(wm.y, dm1, gc.y);
    ull dm2 = fadd2(fmul2(s2, dr), fmul2(r2, ds));
    ull g   = ffma2(cb.wf[12], dm1, cb.gwf[o]);
    g2[o]   = ffma2(cb.wf[13], dm2, g);
  }
  float g01a, g01b, g10a, g10b;
  unpk2(g2[0], g01a, g01b);
  unpk2(g2[1], g10a, g10b);

  float d1 = (g01a > 0.f) ? 0.f : (-n6x - X[1]);
  float d7 = (g01b > 0.f) ? 0.f : (-n6y - X[7]);
  float d2 = (g10a > 0.f) ? 0.f : (-n7x - X[2]);
  float d8 = (g10b > 0.f) ? 0.f : (-n7y - X[8]);
  ull D1 = dup2(d1), D2 = dup2(d2), D7 = dup2(d7), D8 = dup2(d8);

  {
    const ulonglong2 c1 = cb.w0p[1], c2 = cb.w0p[2], c7 = cb.w0p[7], c8 = cb.w0p[8];
    p2 = ffma2(c1.x, D1, ffma2(c2.x, D2, ffma2(c7.x, D7, ffma2(c8.x, D8, p2))));
    q2 = ffma2(c1.y, D1, ffma2(c2.y, D2, ffma2(c7.y, D7, ffma2(c8.y, D8, q2))));
  }
  {
    const ulonglong2 c1 = cb.w1p[1], c2 = cb.w1p[2], c7 = cb.w1p[7], c8 = cb.w1p[8];
    rl = ffma2(c1.x, D1, ffma2(c2.x, D2, ffma2(c7.x, D7, ffma2(c8.x, D8, rl))));
    sl = ffma2(c1.y, D1, ffma2(c2.y, D2, ffma2(c7.y, D7, ffma2(c8.y, D8, sl))));
  }
  ol = ffma2(cb.wf[1], D1, ffma2(cb.wf[2], D2, ffma2(cb.wf[7], D7, ffma2(cb.wf[8], D8, ol))));

  m1 = fmul2(p2, q2);
  r2 = ffma2(wm.x, m1, rl);
  s2 = ffma2(wm.y, m1, sl);
  ull m2 = fmul2(r2, s2);
  ull o2 = ffma2(cb.wf[12], m1, ol);
  o2 = ffma2(cb.wf[13], m2, o2);
  unpk2(o2, ua0, ua1);
}

// out = ubase + coef*rhs(ueval); 2 HORIZONTALLY-adjacent pixels per thread.
// Same conv rows for both pixels: 6-wide window, 3 LDS.128 per row, constants
// loaded once per tap for both. Pixel-1 accumulators staged to smem so poly
// evaluations run with minimal live registers (no spill).
__global__ __launch_bounds__(256, 4)
void rhs_step(const float* __restrict__ ue, const float* __restrict__ ub,
              float coef, float* __restrict__ out)
{
  __shared__ ull tile[12][68];       // rows h0-2..h0+9, cols w0-2..w0+65 (64-wide tile)
  __shared__ ull scratch[8][256];    // px1 accumulators, lane-major (conflict-free)

  const int tx = threadIdx.x, ty = threadIdx.y;   // 32 x 8
  const int tid = ty*32 + tx;
  const int w0_ = blockIdx.x*64, h0 = blockIdx.y*8, b = blockIdx.z;

  const float* u0 = ue + (size_t)b*2*HH*HH;
  const float* u1 = u0 + HH*HH;

  #pragma unroll
  for (int e = tid; e < 12*68; e += 256) {
    int r = e/68, c = e%68;
    int h = h0 + r - 2; if (h < 0) h += HH; if (h >= HH) h -= HH;
    int w = w0_ + c - 2; if (w < 0) w += HH; if (w >= HH) w -= HH;
    tile[r][c] = pk2(u0[h*HH+w], u1[h*HH+w]);
  }
  __syncthreads();

  const int cx = 2*tx;   // px0 tile col = cx (pixel col w0_+cx), px1 = cx+1

  ull acc0[8], acc1[8];
  #pragma unroll
  for (int d = 0; d < 8; d++) { acc0[d] = 0ull; acc1[d] = 0ull; }

  #pragma unroll
  for (int i = 0; i < 5; i++) {
    // 6-value window, 16B-aligned (row stride 544B, cx even): 3 LDS.128
    const ulonglong2* rp = (const ulonglong2*)&tile[ty+i][cx];
    ulonglong2 v0 = rp[0], v1 = rp[1], v2 = rp[2];
    ull w[6];
    w[0]=v0.x; w[1]=v0.y; w[2]=v1.x; w[3]=v1.y; w[4]=v2.x; w[5]=v2.y;
    #pragma unroll
    for (int j = 0; j < 5; j++) {
      const ulonglong2 k01 = cb.kp[0][i*5+j];
      const ulonglong2 k23 = cb.kp[1][i*5+j];
      const ulonglong2 k45 = cb.kp[2][i*5+j];
      const ull km = cb.kp[1][(4-i)*5+j].x;   // k10 tap, mirrored row -> t7
      acc0[0] = ffma2(k01.x, w[j],   acc0[0]);
      acc0[1] = ffma2(k01.y, w[j],   acc0[1]);
      acc0[2] = ffma2(k23.x, w[j],   acc0[2]);
      acc0[3] = ffma2(k23.y, w[j],   acc0[3]);
      acc0[4] = ffma2(k45.x, w[j],   acc0[4]);
      acc0[5] = ffma2(k45.y, w[j],   acc0[5]);
      acc0[6] = ffma2(k01.y, w[4-j], acc0[6]);   // t6: width mirror
      acc0[7] = ffma2(km,    w[j],   acc0[7]);   // t7: height mirror
      acc1[0] = ffma2(k01.x, w[j+1], acc1[0]);
      acc1[1] = ffma2(k01.y, w[j+1], acc1[1]);
      acc1[2] = ffma2(k23.x, w[j+1], acc1[2]);
      acc1[3] = ffma2(k23.y, w[j+1], acc1[3]);
      acc1[4] = ffma2(k45.x, w[j+1], acc1[4]);
      acc1[5] = ffma2(k45.y, w[j+1], acc1[5]);
      acc1[6] = ffma2(k01.y, w[5-j], acc1[6]);
      acc1[7] = ffma2(km,    w[j+1], acc1[7]);
    }
  }

  // Park px1 accumulators in smem; barrier stops ptxas keeping them live.
  #pragma unroll
  for (int d = 0; d < 8; d++) scratch[d][tid] = acc1[d];
  asm volatile("" ::: "memory");

  const int h = h0 + ty, wc = w0_ + cx;
  const size_t i0 = ((size_t)(b*2))*HH*HH + (size_t)h*HH + wc;

  {
    float a0, a1;
    poly_pixel(acc0, a0, a1);
    out[i0]         = ub[i0]         + coef*a0;
    out[i0 + HH*HH] = ub[i0 + HH*HH] + coef*a1;
  }

  ull accr[8];
  #pragma unroll
  for (int d = 0; d < 8; d++) accr[d] = scratch[d][tid];
  {
    float a0, a1;
    poly_pixel(accr, a0, a1);
    out[i0 + 1]         = ub[i0 + 1]         + coef*a0;
    out[i0 + 1 + HH*HH] = ub[i0 + 1 + HH*HH] + coef*a1;
  }
}

extern "C" void kernel_launch(void* const* d_in, const int* in_sizes, int n_in,
                              void* d_out, int out_size)
{
  (void)in_sizes; (void)n_in; (void)out_size;
  const float* init = (const float*)d_in[0];
  const float* kern = (const float*)d_in[1];
  const float* w0   = (const float*)d_in[2];
  const float* b0   = (const float*)d_in[3];
  const float* w1   = (const float*)d_in[4];
  const float* b1   = (const float*)d_in[5];
  const float* wf   = (const float*)d_in[6];
  const float* bf   = (const float*)d_in[7];
  float* out = (float*)d_out;

  void *puh, *pua, *pub, *pstage;
  cudaGetSymbolAddress(&puh, g_uh);
  cudaGetSymbolAddress(&pua, g_ua);
  cudaGetSymbolAddress(&pub, g_ub);
  cudaGetSymbolAddress(&pstage, g_stage);

  prep_kernel<<<1, 128>>>(kern, w0, b0, w1, b1, wf, bf);
  cudaMemcpyToSymbolAsync(cb, pstage, sizeof(ConstBlob), 0, cudaMemcpyDeviceToDevice, 0);

  dim3 grid(HH/64, HH/8, BB);
  dim3 block(32, 8);

  const float DT = 0.2f;
  const float* ucur = init;
  for (int s = 0; s < 5; s++) {
    float* un = (s == 4) ? out : ((s & 1) ? (float*)pub : (float*)pua);
    rhs_step<<<grid, block>>>(ucur, ucur, DT*0.5f, (float*)puh);
    rhs_step<<<grid, block>>>((float*)puh, ucur, DT, un);
    ucur = un;
  }
}

// round 8
// speedup vs baseline: 2.3629x; 1.7579x over previous
#include <cuda_runtime.h>

typedef unsigned long long ull;

#define HH 192
#define BB 16
#define NPIX (BB*2*HH*HH)

// ---------- packed f32x2 helpers (sm_103a) ----------
__device__ __forceinline__ ull pk2(float x, float y){ ull r; asm("mov.b64 %0,{%1,%2};":"=l"(r):"f"(x),"f"(y)); return r; }
__device__ __forceinline__ ull dup2(float x){ return pk2(x,x); }
__device__ __forceinline__ void unpk2(ull v, float&x, float&y){ asm("mov.b64 {%0,%1},%2;":"=f"(x),"=f"(y):"l"(v)); }
__device__ __forceinline__ ull ffma2(ull a, ull b, ull c){ ull d; asm("fma.rn.f32x2 %0,%1,%2,%3;":"=l"(d):"l"(a),"l"(b),"l"(c)); return d; }
__device__ __forceinline__ ull fmul2(ull a, ull b){ ull d; asm("mul.rn.f32x2 %0,%1,%2;":"=l"(d):"l"(a),"l"(b)); return d; }
__device__ __forceinline__ ull fadd2(ull a, ull b){ ull d; asm("add.rn.f32x2 %0,%1,%2;":"=l"(d):"l"(a),"l"(b)); return d; }

// ---------- packed constants, 16B-vectorized ----------
struct ConstBlob {
  ulonglong2 kp[3][25];  // kp[p][i*5+j] = (stencil 2p, stencil 2p+1) tap, lanes dup
  ulonglong2 w0p[12];    // .x = p weight(i), .y = q weight(i); lanes = poly k0,k1
  ulonglong2 w1p[13];    // .x = r, .y = s
  ulonglong2 b01;        // .x = b0(p), .y = b0(q)
  ulonglong2 b11;        // .x = b1(r), .y = b1(s)
  ulonglong2 gw0p[2];    // [off-1]; .x = u=0 pack, .y = u=1 pack
  ulonglong2 gw1p[2];
  ull wf[14];
  ull bf;
  ull gwf[2];
};

__constant__ ConstBlob cb;
__device__ ConstBlob g_stage;
__device__ float g_uh[NPIX];
__device__ float g_ua[NPIX];
__device__ float g_ub[NPIX];

__global__ void prep_kernel(const float* __restrict__ kern,
                            const float* __restrict__ w0, const float* __restrict__ b0,
                            const float* __restrict__ w1, const float* __restrict__ b1,
                            const float* __restrict__ wf, const float* __restrict__ bf)
{
  int t = threadIdx.x;
  const double dDX = 0.0327249;
  const float s1 = (float)(1.0/dDX);
  const float s2 = (float)(1.0/(dDX*dDX));
  const float sc[6] = {1.f, s1, s1, s2, s2, s2};
  if (t < 75) {
    int p = t/25, e = t%25;
    int d0 = 2*p, d1 = 2*p+1;
    ulonglong2 v;
    v.x = dup2(kern[d0*25 + e] * sc[d0]);
    v.y = dup2(kern[d1*25 + e] * sc[d1]);
    g_stage.kp[p][e] = v;
  }
  if (t == 0) {
    for (int i = 0; i < 12; i++) {
      ulonglong2 a;
      a.x = pk2(w0[i],    w0[24+i]);
      a.y = pk2(w0[12+i], w0[24+12+i]);
      g_stage.w0p[i] = a;
    }
    for (int i = 0; i < 13; i++) {
      ulonglong2 a;
      a.x = pk2(w1[i],    w1[26+i]);
      a.y = pk2(w1[13+i], w1[26+13+i]);
      g_stage.w1p[i] = a;
    }
    { ulonglong2 a; a.x = pk2(b0[0], b0[2]); a.y = pk2(b0[1], b0[3]); g_stage.b01 = a; }
    { ulonglong2 a; a.x = pk2(b1[0], b1[2]); a.y = pk2(b1[1], b1[3]); g_stage.b11 = a; }
    for (int i = 0; i < 14; i++) g_stage.wf[i] = pk2(wf[i], wf[14+i]);
    g_stage.bf = pk2(bf[0], bf[1]);
    for (int o = 0; o < 2; o++) {
      ulonglong2 a, c;
      a.x = pk2(w0[1+o],      w0[24 + 7+o]);
      a.y = pk2(w0[12 + 1+o], w0[24 + 12 + 7+o]);
      g_stage.gw0p[o] = a;
      c.x = pk2(w1[1+o],      w1[26 + 7+o]);
      c.y = pk2(w1[13 + 1+o], w1[26 + 13 + 7+o]);
      g_stage.gw1p[o] = c;
      g_stage.gwf[o] = pk2(wf[1+o], wf[14 + 7+o]);
    }
  }
}

// out = ubase + coef * rhs(ueval); 1 pixel/thread, 32x6 blocks, 8 blocks/SM
__global__ __launch_bounds__(192, 8)
void rhs_step(const float* __restrict__ ue, const float* __restrict__ ub,
              float coef, float* __restrict__ out)
{
  __shared__ ull tile[10][36];   // (c0,c1) packed, rows h0-2 .. h0+7

  const int tx = threadIdx.x, ty = threadIdx.y;
  const int tid = ty*32 + tx;
  const int w0_ = blockIdx.x*32, h0 = blockIdx.y*6, b = blockIdx.z;

  const float* u0 = ue + (size_t)b*2*HH*HH;
  const float* u1 = u0 + HH*HH;

  #pragma unroll
  for (int e = tid; e < 10*36; e += 192) {
    int r = e/36, c = e%36;
    int h = h0 + r - 2; if (h < 0) h += HH; if (h >= HH) h -= HH;
    int w = w0_ + c - 2; if (w < 0) w += HH; if (w >= HH) w -= HH;
    tile[r][c] = pk2(u0[h*HH+w], u1[h*HH+w]);
  }
  __syncthreads();

  // ---- 6 base correlations + 2 mirrored (constants shared via vector loads) ----
  ull a0=0ull,a1=0ull,a2=0ull,a3=0ull,a4=0ull,a5=0ull,t6=0ull,t7=0ull;
  #pragma unroll
  for (int i = 0; i < 5; i++) {
    ull w[5];
    #pragma unroll
    for (int j = 0; j < 5; j++) w[j] = tile[ty+i][tx+j];
    #pragma unroll
    for (int j = 0; j < 5; j++) {
      const ulonglong2 k01 = cb.kp[0][i*5+j];
      const ulonglong2 k23 = cb.kp[1][i*5+j];
      const ulonglong2 k45 = cb.kp[2][i*5+j];
      a0 = ffma2(k01.x, w[j], a0);
      a1 = ffma2(k01.y, w[j], a1);
      a2 = ffma2(k23.x, w[j], a2);
      a3 = ffma2(k23.y, w[j], a3);
      a4 = ffma2(k45.x, w[j], a4);
      a5 = ffma2(k45.y, w[j], a5);
      // f01 = -sum k01tap(i,j)*w(i,4-j): width mirror
      t6 = ffma2(k01.y, w[4-j], t6);
      // f10 = -sum k10tap(i,j)*w(4-i,j): height mirror (const CSE across unroll)
      t7 = ffma2(cb.kp[1][(4-i)*5+j].x, w[j], t7);
    }
  }

  float X[12];
  unpk2(a0, X[0], X[6]); unpk2(a1, X[1], X[7]); unpk2(a2, X[2], X[8]);
  unpk2(a3, X[3], X[9]); unpk2(a4, X[4], X[10]); unpk2(a5, X[5], X[11]);
  float n6x, n6y, n7x, n7y;
  unpk2(t6, n6x, n6y);   // f01 = -n6
  unpk2(t7, n7x, n7y);   // f10 = -n7

  // ---- poly linear parts at base (lanes = poly k0,k1) ----
  ull p2 = cb.b01.x, q2 = cb.b01.y, rl = cb.b11.x, sl = cb.b11.y, ol = cb.bf;
  #pragma unroll
  for (int i = 0; i < 12; i++) {
    ull xd = dup2(X[i]);
    const ulonglong2 wa = cb.w0p[i];
    const ulonglong2 wb = cb.w1p[i];
    p2 = ffma2(wa.x, xd, p2);
    q2 = ffma2(wa.y, xd, q2);
    rl = ffma2(wb.x, xd, rl);
    sl = ffma2(wb.y, xd, sl);
    ol = ffma2(cb.wf[i], xd, ol);
  }
  const ulonglong2 wm = cb.w1p[12];   // m1 coefficients for (r,s)
  ull m1 = fmul2(p2, q2);
  ull r2 = ffma2(wm.x, m1, rl);
  ull s2 = ffma2(wm.y, m1, sl);

  // ---- analytic gradient at base: d(poly_k)/dX[k*6+off], off=1,2 ----
  ull g2[2];
  #pragma unroll
  for (int o = 0; o < 2; o++) {
    const ulonglong2 ga = cb.gw0p[o];
    const ulonglong2 gc = cb.gw1p[o];
    ull dm1 = fadd2(fmul2(q2, ga.x), fmul2(p2, ga.y));
    ull dr  = ffma2(wm.x, dm1, gc.x);
    ull ds  = ffma2(wm.y, dm1, gc.y);
    ull dm2 = fadd2(fmul2(s2, dr), fmul2(r2, ds));
    ull g   = ffma2(cb.wf[12], dm1, cb.gwf[o]);
    g2[o]   = ffma2(cb.wf[13], dm2, g);
  }
  float g01a, g01b, g10a, g10b;
  unpk2(g2[0], g01a, g01b);
  unpk2(g2[1], g10a, g10b);

  // upwind deltas (0 if keep base, else flipped - base); flipped = -n
  float d1 = (g01a > 0.f) ? 0.f : (-n6x - X[1]);
  float d7 = (g01b > 0.f) ? 0.f : (-n6y - X[7]);
  float d2 = (g10a > 0.f) ? 0.f : (-n7x - X[2]);
  float d8 = (g10b > 0.f) ? 0.f : (-n7y - X[8]);
  ull D1 = dup2(d1), D2 = dup2(d2), D7 = dup2(d7), D8 = dup2(d8);

  // ---- delta-update linear parts to Xsel, finish poly ----
  {
    const ulonglong2 c1 = cb.w0p[1], c2 = cb.w0p[2], c7 = cb.w0p[7], c8 = cb.w0p[8];
    p2 = ffma2(c1.x, D1, ffma2(c2.x, D2, ffma2(c7.x, D7, ffma2(c8.x, D8, p2))));
    q2 = ffma2(c1.y, D1, ffma2(c2.y, D2, ffma2(c7.y, D7, ffma2(c8.y, D8, q2))));
  }
  {
    const ulonglong2 c1 = cb.w1p[1], c2 = cb.w1p[2], c7 = cb.w1p[7], c8 = cb.w1p[8];
    rl = ffma2(c1.x, D1, ffma2(c2.x, D2, ffma2(c7.x, D7, ffma2(c8.x, D8, rl))));
    sl = ffma2(c1.y, D1, ffma2(c2.y, D2, ffma2(c7.y, D7, ffma2(c8.y, D8, sl))));
  }
  ol = ffma2(cb.wf[1], D1, ffma2(cb.wf[2], D2, ffma2(cb.wf[7], D7, ffma2(cb.wf[8], D8, ol))));

  m1 = fmul2(p2, q2);
  r2 = ffma2(wm.x, m1, rl);
  s2 = ffma2(wm.y, m1, sl);
  ull m2 = fmul2(r2, s2);
  ull o2 = ffma2(cb.wf[12], m1, ol);
  o2 = ffma2(cb.wf[13], m2, o2);

  float ua0, ua1;
  unpk2(o2, ua0, ua1);

  const int h = h0 + ty, w = w0_ + tx;
  const size_t i0 = ((size_t)(b*2))*HH*HH + (size_t)h*HH + w;
  out[i0]         = ub[i0]         + coef*ua0;
  out[i0 + HH*HH] = ub[i0 + HH*HH] + coef*ua1;
}

extern "C" void kernel_launch(void* const* d_in, const int* in_sizes, int n_in,
                              void* d_out, int out_size)
{
  (void)in_sizes; (void)n_in; (void)out_size;
  const float* init = (const float*)d_in[0];
  const float* kern = (const float*)d_in[1];
  const float* w0   = (const float*)d_in[2];
  const float* b0   = (const float*)d_in[3];
  const float* w1   = (const float*)d_in[4];
  const float* b1   = (const float*)d_in[5];
  const float* wf   = (const float*)d_in[6];
  const float* bf   = (const float*)d_in[7];
  float* out = (float*)d_out;

  void *puh, *pua, *pub, *pstage;
  cudaGetSymbolAddress(&puh, g_uh);
  cudaGetSymbolAddress(&pua, g_ua);
  cudaGetSymbolAddress(&pub, g_ub);
  cudaGetSymbolAddress(&pstage, g_stage);

  prep_kernel<<<1, 128>>>(kern, w0, b0, w1, b1, wf, bf);
  cudaMemcpyToSymbolAsync(cb, pstage, sizeof(ConstBlob), 0, cudaMemcpyDeviceToDevice, 0);

  dim3 grid(HH/32, HH/6, BB);
  dim3 block(32, 6);

  const float DT = 0.2f;
  const float* ucur = init;
  for (int s = 0; s < 5; s++) {
    float* un = (s == 4) ? out : ((s & 1) ? (float*)pub : (float*)pua);
    rhs_step<<<grid, block>>>(ucur, ucur, DT*0.5f, (float*)puh);
    rhs_step<<<grid, block>>>((float*)puh, ucur, DT, un);
    ucur = un;
  }
}